// round 8
// baseline (speedup 1.0000x reference)
#include <cuda_runtime.h>
#include <cuda_fp16.h>
#include <math.h>

#define B_   4096
#define T_   200
#define E_   64
#define H1_  80
#define H2_  40
#define NT   256

// strides (bytes): K/M rows = 144B (144%128=16 -> ldmatrix conflict-free)
//                  W2 rows  = 176B (176%128=48 -> conflict-free)
#define KS  144
#define HS  176

// ---------------- smem layout (bytes)
#define OFF_K   0                       // [208][72]h  29952  (13 m16 tiles max)
#define OFF_MHI 29952                   // [80][72]h   11520
#define OFF_MLO 41472                   // [80][72]h   11520
#define OFF_W2  52992                   // [40][88]h    7040
#define OFF_C   60032                   // f32[80]
#define OFF_B2  60352                   // f32[40]
#define OFF_WD  60512                   // f32[40]
#define OFF_Q   60672                   // f32[64]
#define OFF_SP  60928                   // f32[8*64]
#define OFF_BD  62976
#define SMEM_TOTAL 63104                // x3 CTAs = 185KB <= 228KB/SM

__device__ __forceinline__ unsigned smem_u32(const void* p) {
    unsigned a; asm("{ .reg .u64 t; cvta.to.shared.u64 t, %1; cvt.u32.u64 %0, t; }" : "=r"(a) : "l"(p));
    return a;
}
__device__ __forceinline__ void ldmx4(unsigned a[4], unsigned addr) {
    asm volatile("ldmatrix.sync.aligned.m8n8.x4.shared.b16 {%0,%1,%2,%3}, [%4];"
                 : "=r"(a[0]), "=r"(a[1]), "=r"(a[2]), "=r"(a[3]) : "r"(addr));
}
__device__ __forceinline__ void ldmx2(unsigned a[2], unsigned addr) {
    asm volatile("ldmatrix.sync.aligned.m8n8.x2.shared.b16 {%0,%1}, [%2];"
                 : "=r"(a[0]), "=r"(a[1]) : "r"(addr));
}
__device__ __forceinline__ void mma16816(float d[4], const unsigned a[4], const unsigned b[2]) {
    asm volatile("mma.sync.aligned.m16n8k16.row.col.f32.f16.f16.f32 "
                 "{%0,%1,%2,%3},{%4,%5,%6,%7},{%8,%9},{%0,%1,%2,%3};"
                 : "+f"(d[0]), "+f"(d[1]), "+f"(d[2]), "+f"(d[3])
                 : "r"(a[0]), "r"(a[1]), "r"(a[2]), "r"(a[3]), "r"(b[0]), "r"(b[1]));
}
__device__ __forceinline__ float sigf(float x) { return __fdividef(1.f, 1.f + __expf(-x)); }

// ---------------- device scratch
__device__ float    g_Wkt[H1_ * E_];   // (W1b - W1c)^T [h][e]
__device__ float    g_Wpt[H1_ * E_];   // W1d^T        [h][e]
__device__ float    g_Wqt[H1_ * E_];   // (W1a + W1c)^T[h][e]
__device__ unsigned g_W2h[1760];       // W2^T fp16 image [40 rows j][88 cols h], u32 words
__device__ int      g_len[B_];

// ---------------------------------------------------------------------------
__global__ void prep(const float* __restrict__ W1, const float* __restrict__ W2,
                     const int* __restrict__ raw) {
    int blk = blockIdx.x, tid = threadIdx.x;
    if (blk < 20) {                                   // W1 folds, transposed
        int idx = blk * 256 + tid;
        if (idx >= H1_ * E_) return;
        int h = idx >> 6, e = idx & 63;
        float wa = W1[(e         ) * H1_ + h];
        float wb = W1[(E_     + e) * H1_ + h];
        float wc = W1[(2 * E_ + e) * H1_ + h];
        float wd = W1[(3 * E_ + e) * H1_ + h];
        g_Wqt[idx] = wa + wc;
        g_Wkt[idx] = wb - wc;
        g_Wpt[idx] = wd;
    } else if (blk == 20) {                           // keys_length dtype sniff + clamp
        int any = 0;
        for (int i = 2 * tid + 1; i < B_; i += 512) any |= raw[i];
        int has_odd = __syncthreads_or(any);
        int is64 = (has_odd == 0);
        for (int i = tid; i < B_; i += 256) {
            int v = is64 ? raw[2 * i] : raw[i];
            g_len[i] = v < 0 ? 0 : (v > T_ ? T_ : v);
        }
    } else {                                          // W2^T fp16 image
        int idx = (blk - 21) * 256 + tid;
        if (idx < 1760) {
            int j = idx / 44, w = idx - j * 44;
            int h0 = 2 * w;
            float v0 = (h0     < H1_) ? W2[h0 * H2_ + j]       : 0.f;
            float v1 = (h0 + 1 < H1_) ? W2[(h0 + 1) * H2_ + j] : 0.f;
            __half2 p = __floats2half2_rn(v0, v1);
            g_W2h[idx] = *(unsigned*)&p;
        }
    }
}

// ---------------------------------------------------------------------------
extern __shared__ char smem[];

__global__ void __launch_bounds__(NT, 3)
din_mma(const float* __restrict__ query, const float* __restrict__ keys,
        const float* __restrict__ b1v,   const float* __restrict__ b2v,
        const float* __restrict__ Wdv,   const float* __restrict__ bdv,
        float* __restrict__ out)
{
    const int tid  = threadIdx.x;
    const int wid  = tid >> 5;
    const int lane = tid & 31;
    const int b    = blockIdx.x;
    const int len  = g_len[b];
    const unsigned sb = smem_u32(smem);

    // fragment lane constants
    const int g     = lane >> 2;
    const int t2    = (lane & 3) * 2;
    const int arow  = (lane & 7) + ((lane >> 3) & 1) * 8;
    const int acolB = ((lane >> 4) * 8) * 2;
    const int brow  = lane & 7;
    const int bcolB = ((lane >> 3) & 1) * 16;

    float* sQ  = (float*)(smem + OFF_Q);
    float* sC  = (float*)(smem + OFF_C);
    float* sB2 = (float*)(smem + OFF_B2);
    float* sWd = (float*)(smem + OFF_WD);
    float* sSp = (float*)(smem + OFF_SP);

    // ---- phase 0: small vectors
    if (tid < E_) sQ[tid] = query[b * E_ + tid];
    if (tid >= 64 && tid < 64 + H2_) { int j = tid - 64; sB2[j] = b2v[j]; sWd[j] = Wdv[j]; }
    if (tid == 104) *(float*)(smem + OFF_BD) = bdv[0];
    __syncthreads();

    // ---- phase 1: M hi/lo, C, W2 copy (weights), and K convert (all rows)
    for (int idx = tid; idx < H1_ * E_; idx += NT) {
        int h = idx >> 6, e = idx & 63;
        float v = g_Wkt[idx] + sQ[e] * g_Wpt[idx];
        __half hi = __float2half_rn(v);
        __half lo = __float2half_rn(v - __half2float(hi));
        *(__half*)(smem + OFF_MHI + h * KS + e * 2) = hi;
        *(__half*)(smem + OFF_MLO + h * KS + e * 2) = lo;
    }
    if (tid < H1_) {
        const float4* wq = (const float4*)&g_Wqt[tid * E_];
        const float4* q4 = (const float4*)sQ;
        float c = b1v[tid];
        #pragma unroll
        for (int i = 0; i < 16; i++) {
            float4 w = wq[i], q = q4[i];
            c += w.x * q.x + w.y * q.y + w.z * q.z + w.w * q.w;
        }
        sC[tid] = c;
    }
    for (int i = tid; i < 1760; i += NT) ((unsigned*)(smem + OFF_W2))[i] = g_W2h[i];

    const int mt = (len + 15) >> 4;        // m16 tiles (<=13)
    {
        // zero pad rows [len, mt*16)
        int zcnt = (mt * 16 - len) * (KS / 4);
        unsigned* zh = (unsigned*)(smem + OFF_K + len * KS);
        for (int i = tid; i < zcnt; i += NT) zh[i] = 0;
        // convert K rows [0, len): fp32 -> fp16
        const float4* kb = (const float4*)(keys + (size_t)b * (T_ * E_));
        int n4 = len * 16;
        for (int i4 = tid; i4 < n4; i4 += NT) {
            float4 v = kb[i4];
            int tl = i4 >> 4, e4 = (i4 & 15) << 2;
            __half2 h0 = __floats2half2_rn(v.x, v.y);
            __half2 h1 = __floats2half2_rn(v.z, v.w);
            *(uint2*)(smem + OFF_K + (unsigned)tl * KS + (unsigned)e4 * 2) =
                make_uint2(*(unsigned*)&h0, *(unsigned*)&h1);
        }
    }
    __syncthreads();

    const float bd = *(float*)(smem + OFF_BD);
    float acc0 = 0.f, acc1 = 0.f;          // pooling accumulators (e = 2*lane, 2*lane+1)

    // per-lane combined ldmatrix.x4 bases:
    //  - M: lanes 0-15 -> Mhi (matrices 0,1 = k0-7/k8-15), lanes 16-31 -> Mlo (2,3)
    //  - W2: lanes 0-15 -> n-tile pair lo, lanes 16-31 -> pair hi
    const unsigned bComb = sb + OFF_MHI + ((lane & 16) ? (OFF_MLO - OFF_MHI) : 0u)
                         + (unsigned)brow * KS + bcolB;
    const unsigned wComb = sb + OFF_W2 + ((lane & 16) ? 8u * HS : 0u)
                         + (unsigned)brow * HS + bcolB;
    const unsigned w4Base = sb + OFF_W2 + (unsigned)(4 * 8 + brow) * HS + bcolB;
    const float* kbp = keys + (size_t)b * (T_ * E_) + 2 * lane;

    // ---- fused layer1+layer2+pooling: warps process tiles independently (no barriers)
    for (int tl = wid; tl < mt; tl += 8) {
        unsigned Ah[4][4];
        unsigned aB = sb + OFF_K + (unsigned)(tl * 16 + arow) * KS + acolB;
        #pragma unroll
        for (int kt = 0; kt < 4; kt++) ldmx4(Ah[kt], aB + kt * 32);

        float D2[5][4];
        #pragma unroll
        for (int n = 0; n < 5; n++)
            #pragma unroll
            for (int r = 0; r < 4; r++) D2[n][r] = 0.f;

        #pragma unroll
        for (int kc = 0; kc < 5; kc++) {           // k-chunk = nt pair (2kc, 2kc+1)
            float De[4] = {0.f,0.f,0.f,0.f};
            float Do[4] = {0.f,0.f,0.f,0.f};
            unsigned bE = bComb + (unsigned)(kc * 16) * KS;
            unsigned bO = bE + 8u * KS;
            #pragma unroll
            for (int kt = 0; kt < 4; kt++) {
                unsigned Be[4], Bo[4];             // r0,r1 = Bhi; r2,r3 = Blo
                ldmx4(Be, bE + kt * 32);
                ldmx4(Bo, bO + kt * 32);
                mma16816(De, Ah[kt], Be);
                mma16816(Do, Ah[kt], Bo);
                mma16816(De, Ah[kt], Be + 2);
                mma16816(Do, Ah[kt], Bo + 2);
            }
            // epilogue -> A2 fragment (rows g/g+8, k16 chunk kc of layer-2)
            int ce = kc * 16 + t2;
            float c0 = sC[ce], c1 = sC[ce + 1], c2 = sC[ce + 8], c3 = sC[ce + 9];
            __half2 a0 = __floats2half2_rn(sigf(De[0] + c0), sigf(De[1] + c1));
            __half2 a1 = __floats2half2_rn(sigf(De[2] + c0), sigf(De[3] + c1));
            __half2 a2 = __floats2half2_rn(sigf(Do[0] + c2), sigf(Do[1] + c3));
            __half2 a3 = __floats2half2_rn(sigf(Do[2] + c2), sigf(Do[3] + c3));
            unsigned A2[4] = { *(unsigned*)&a0, *(unsigned*)&a1,
                               *(unsigned*)&a2, *(unsigned*)&a3 };
            unsigned Bw01[4], Bw23[4], Bw4[2];
            ldmx4(Bw01, wComb + (unsigned)(kc * 32));
            ldmx4(Bw23, wComb + 16u * HS + (unsigned)(kc * 32));
            ldmx2(Bw4,  w4Base + (unsigned)(kc * 32));
            mma16816(D2[0], A2, Bw01);
            mma16816(D2[1], A2, Bw01 + 2);
            mma16816(D2[2], A2, Bw23);
            mma16816(D2[3], A2, Bw23 + 2);
            mma16816(D2[4], A2, Bw4);
        }

        // ---- scores: sigmoid(D2 + b2) . Wd, quad-reduce (all lanes get quad sum)
        float p0 = 0.f, p1 = 0.f;
        #pragma unroll
        for (int n = 0; n < 5; n++) {
            int j0 = n * 8 + t2;
            float w0 = sWd[j0], w1 = sWd[j0 + 1];
            float bb0 = sB2[j0], bb1 = sB2[j0 + 1];
            p0 += sigf(D2[n][0] + bb0) * w0 + sigf(D2[n][1] + bb1) * w1;
            p1 += sigf(D2[n][2] + bb0) * w0 + sigf(D2[n][3] + bb1) * w1;
        }
        p0 += __shfl_xor_sync(0xFFFFFFFFu, p0, 1);
        p0 += __shfl_xor_sync(0xFFFFFFFFu, p0, 2);
        p1 += __shfl_xor_sync(0xFFFFFFFFu, p1, 1);
        p1 += __shfl_xor_sync(0xFFFFFFFFu, p1, 2);
        p0 += bd;                                   // score rows tl*16 + g
        p1 += bd;                                   // score rows tl*16 + g + 8

        // ---- pooling for this tile's rows (global keys, L2-hot; exact fp32)
        int base = tl * 16;
        int nr = len - base; if (nr > 16) nr = 16;
        const float* kr = kbp + (size_t)base * E_;
        #pragma unroll
        for (int r = 0; r < 16; r++) {
            if (r >= nr) break;
            float sr = (r < 8) ? __shfl_sync(0xFFFFFFFFu, p0, 4 * r)
                               : __shfl_sync(0xFFFFFFFFu, p1, 4 * (r - 8));
            float2 kv = *(const float2*)(kr + (size_t)r * E_);
            acc0 += sr * kv.x;
            acc1 += sr * kv.y;
        }
    }

    // ---- final reduce across warps
    sSp[wid * 64 + 2 * lane]     = acc0;
    sSp[wid * 64 + 2 * lane + 1] = acc1;
    __syncthreads();
    if (tid < E_) {
        float o = 0.f;
        #pragma unroll
        for (int w = 0; w < 8; w++) o += sSp[w * 64 + tid];
        out[b * E_ + tid] = o;
    }
}

// ---------------------------------------------------------------------------
extern "C" void kernel_launch(void* const* d_in, const int* in_sizes, int n_in,
                              void* d_out, int out_size) {
    const float* query = (const float*)d_in[0];
    const float* keys  = (const float*)d_in[1];
    const int*   klen  = (const int*)  d_in[2];
    const float* W1    = (const float*)d_in[3];
    const float* b1    = (const float*)d_in[4];
    const float* W2    = (const float*)d_in[5];
    const float* b2    = (const float*)d_in[6];
    const float* Wd    = (const float*)d_in[7];
    const float* bd    = (const float*)d_in[8];
    float* out = (float*)d_out;

    cudaFuncSetAttribute(din_mma, cudaFuncAttributeMaxDynamicSharedMemorySize, SMEM_TOTAL);

    prep<<<28, 256>>>(W1, W2, klen);
    din_mma<<<B_, NT, SMEM_TOTAL>>>(query, keys, b1, b2, Wd, bd, out);
}

// round 9
// speedup vs baseline: 1.2580x; 1.2580x over previous
#include <cuda_runtime.h>
#include <cuda_fp16.h>
#include <math.h>

#define B_   4096
#define T_   200
#define E_   64
#define H1_  80
#define H2_  40
#define NT   256
#define HROWS 128
#define HALF  128

// strides (bytes): K/M rows = 144B (144%128=16 -> ldmatrix conflict-free)
//                  W2 rows  = 176B (176%128=48 -> conflict-free)
#define KS  144
#define HS  176

// ---------------- smem layout (bytes)
#define OFF_K   0                       // [128][72]h  18432
#define OFF_MHI 18432                   // [80][72]h   11520
#define OFF_MLO 29952                   // [80][72]h   11520
#define OFF_W2  41472                   // [40][88]h    7040
#define OFF_C   48512                   // f32[80]
#define OFF_B2  48832                   // f32[40]
#define OFF_WD  48992                   // f32[40]
#define OFF_Q   49152                   // f32[64]
#define OFF_SC  49408                   // f32[128]
#define OFF_SP  49920                   // f32[8*64]
#define OFF_BD  51968
#define SMEM_TOTAL 52096                // x4 CTAs = 208KB <= 228KB/SM

__device__ __forceinline__ unsigned smem_u32(const void* p) {
    unsigned a; asm("{ .reg .u64 t; cvta.to.shared.u64 t, %1; cvt.u32.u64 %0, t; }" : "=r"(a) : "l"(p));
    return a;
}
__device__ __forceinline__ void ldmx4(unsigned a[4], unsigned addr) {
    asm volatile("ldmatrix.sync.aligned.m8n8.x4.shared.b16 {%0,%1,%2,%3}, [%4];"
                 : "=r"(a[0]), "=r"(a[1]), "=r"(a[2]), "=r"(a[3]) : "r"(addr));
}
__device__ __forceinline__ void ldmx2(unsigned a[2], unsigned addr) {
    asm volatile("ldmatrix.sync.aligned.m8n8.x2.shared.b16 {%0,%1}, [%2];"
                 : "=r"(a[0]), "=r"(a[1]) : "r"(addr));
}
__device__ __forceinline__ void mma16816(float d[4], const unsigned a[4], const unsigned b[2]) {
    asm volatile("mma.sync.aligned.m16n8k16.row.col.f32.f16.f16.f32 "
                 "{%0,%1,%2,%3},{%4,%5,%6,%7},{%8,%9},{%0,%1,%2,%3};"
                 : "+f"(d[0]), "+f"(d[1]), "+f"(d[2]), "+f"(d[3])
                 : "r"(a[0]), "r"(a[1]), "r"(a[2]), "r"(a[3]), "r"(b[0]), "r"(b[1]));
}
__device__ __forceinline__ float sigf(float x) { return __fdividef(1.f, 1.f + __expf(-x)); }

// ---------------- device scratch
__device__ float    g_Wkt[H1_ * E_];   // (W1b - W1c)^T [h][e]
__device__ float    g_Wpt[H1_ * E_];   // W1d^T        [h][e]
__device__ float    g_Wqt[H1_ * E_];   // (W1a + W1c)^T[h][e]
__device__ unsigned g_W2h[1760];       // W2^T fp16 image [40 rows j][88 cols h], u32 words
__device__ int      g_len[B_];

// ---------------------------------------------------------------------------
__global__ void prep(const float* __restrict__ W1, const float* __restrict__ W2,
                     const int* __restrict__ raw) {
    int blk = blockIdx.x, tid = threadIdx.x;
    if (blk < 20) {                                   // W1 folds, transposed
        int idx = blk * 256 + tid;
        if (idx >= H1_ * E_) return;
        int h = idx >> 6, e = idx & 63;
        float wa = W1[(e         ) * H1_ + h];
        float wb = W1[(E_     + e) * H1_ + h];
        float wc = W1[(2 * E_ + e) * H1_ + h];
        float wd = W1[(3 * E_ + e) * H1_ + h];
        g_Wqt[idx] = wa + wc;
        g_Wkt[idx] = wb - wc;
        g_Wpt[idx] = wd;
    } else if (blk == 20) {                           // keys_length dtype sniff + clamp
        int any = 0;
        for (int i = 2 * tid + 1; i < B_; i += 512) any |= raw[i];
        int has_odd = __syncthreads_or(any);
        int is64 = (has_odd == 0);
        for (int i = tid; i < B_; i += 256) {
            int v = is64 ? raw[2 * i] : raw[i];
            g_len[i] = v < 0 ? 0 : (v > T_ ? T_ : v);
        }
    } else {                                          // W2^T fp16 image
        int idx = (blk - 21) * 256 + tid;
        if (idx < 1760) {
            int j = idx / 44, w = idx - j * 44;
            int h0 = 2 * w;
            float v0 = (h0     < H1_) ? W2[h0 * H2_ + j]       : 0.f;
            float v1 = (h0 + 1 < H1_) ? W2[(h0 + 1) * H2_ + j] : 0.f;
            __half2 p = __floats2half2_rn(v0, v1);
            g_W2h[idx] = *(unsigned*)&p;
        }
    }
}

// ---------------------------------------------------------------------------
extern __shared__ char smem[];

__global__ void __launch_bounds__(NT, 4)
din_mma(const float* __restrict__ query, const float* __restrict__ keys,
        const float* __restrict__ b1v,   const float* __restrict__ b2v,
        const float* __restrict__ Wdv,   const float* __restrict__ bdv,
        float* __restrict__ out)
{
    const int tid  = threadIdx.x;
    const int wid  = tid >> 5;
    const int lane = tid & 31;
    const int b    = blockIdx.x;
    const int len  = g_len[b];
    const unsigned sb = smem_u32(smem);

    // fragment lane constants
    const int g     = lane >> 2;
    const int t2    = (lane & 3) * 2;
    const int arow  = (lane & 7) + ((lane >> 3) & 1) * 8;
    const int acolB = ((lane >> 4) * 8) * 2;
    const int brow  = lane & 7;
    const int bcolB = ((lane >> 3) & 1) * 16;

    float* sQ  = (float*)(smem + OFF_Q);
    float* sC  = (float*)(smem + OFF_C);
    float* sB2 = (float*)(smem + OFF_B2);
    float* sWd = (float*)(smem + OFF_WD);
    float* sSc = (float*)(smem + OFF_SC);
    float* sSp = (float*)(smem + OFF_SP);

    // ---- phase 0: small vectors
    if (tid < E_) sQ[tid] = query[b * E_ + tid];
    if (tid >= 64 && tid < 64 + H2_) { int j = tid - 64; sB2[j] = b2v[j]; sWd[j] = Wdv[j]; }
    if (tid == 104) *(float*)(smem + OFF_BD) = bdv[0];
    __syncthreads();

    // ---- phase 1: M hi/lo, C, W2 copy
    for (int idx = tid; idx < H1_ * E_; idx += NT) {
        int h = idx >> 6, e = idx & 63;
        float v = g_Wkt[idx] + sQ[e] * g_Wpt[idx];
        __half hi = __float2half_rn(v);
        __half lo = __float2half_rn(v - __half2float(hi));
        *(__half*)(smem + OFF_MHI + h * KS + e * 2) = hi;
        *(__half*)(smem + OFF_MLO + h * KS + e * 2) = lo;
    }
    if (tid < H1_) {
        const float4* wq = (const float4*)&g_Wqt[tid * E_];
        const float4* q4 = (const float4*)sQ;
        float c = b1v[tid];
        #pragma unroll
        for (int i = 0; i < 16; i++) {
            float4 w = wq[i], q = q4[i];
            c += w.x * q.x + w.y * q.y + w.z * q.z + w.w * q.w;
        }
        sC[tid] = c;
    }
    for (int i = tid; i < 1760; i += NT) ((unsigned*)(smem + OFF_W2))[i] = g_W2h[i];
    __syncthreads();

    const float bd = *(float*)(smem + OFF_BD);
    float acc0 = 0.f, acc1 = 0.f;          // pooling accumulators (e = 2*lane, 2*lane+1)

    // per-lane combined ldmatrix.x4 bases:
    //  - M: lanes 0-15 -> Mhi (matrices 0,1 = k0-7 / k8-15), lanes 16-31 -> Mlo (matrices 2,3)
    //  - W2: lanes 0-15 -> n-tile pair lo, lanes 16-31 -> pair hi
    const unsigned bComb = sb + OFF_MHI + ((lane & 16) ? (OFF_MLO - OFF_MHI) : 0u)
                         + (unsigned)brow * KS + bcolB;
    const unsigned wComb = sb + OFF_W2 + ((lane & 16) ? 8u * HS : 0u)
                         + (unsigned)brow * HS + bcolB;
    const unsigned w4Base = sb + OFF_W2 + (unsigned)(4 * 8 + brow) * HS + bcolB;

    for (int hh = 0; hh < 2; hh++) {
        int hlen = len - HALF * hh;
        if (hlen > HALF) hlen = HALF;
        if (hlen <= 0) break;
        const int mt = (hlen + 15) >> 4;   // m16 tiles this half (<=8)

        // ---- convert K half: fp32 -> fp16; zero only rows [hlen, mt*16)
        {
            int zcnt = (mt * 16 - hlen) * (KS / 4);
            unsigned* zh = (unsigned*)(smem + OFF_K + hlen * KS);
            for (int i = tid; i < zcnt; i += NT) zh[i] = 0;
            const float4* kb = (const float4*)(keys + (size_t)b * (T_ * E_) + HALF * hh * E_);
            int n4 = hlen * 16;
            for (int i4 = tid; i4 < n4; i4 += NT) {
                float4 v = kb[i4];
                int tl = i4 >> 4, e4 = (i4 & 15) << 2;
                __half2 h0 = __floats2half2_rn(v.x, v.y);
                __half2 h1 = __floats2half2_rn(v.z, v.w);
                *(uint2*)(smem + OFF_K + (unsigned)tl * KS + (unsigned)e4 * 2) =
                    make_uint2(*(unsigned*)&h0, *(unsigned*)&h1);
            }
        }
        __syncthreads();

        // ---- fused layer1+layer2: warp w owns m-tile w through both layers.
        // A fragments re-loaded per k-chunk (frees 16 regs -> 4 CTAs/SM).
        if (wid < mt) {
            const unsigned aB = sb + OFF_K + (unsigned)(wid * 16 + arow) * KS + acolB;

            float D2[5][4];
            #pragma unroll
            for (int n = 0; n < 5; n++)
                #pragma unroll
                for (int r = 0; r < 4; r++) D2[n][r] = 0.f;

            #pragma unroll
            for (int kc = 0; kc < 5; kc++) {           // k-chunk = nt pair (2kc, 2kc+1)
                float De[4] = {0.f,0.f,0.f,0.f};
                float Do[4] = {0.f,0.f,0.f,0.f};
                unsigned bE = bComb + (unsigned)(kc * 16) * KS;
                unsigned bO = bE + 8u * KS;
                #pragma unroll
                for (int kt = 0; kt < 4; kt++) {
                    unsigned Ah[4], Be[4], Bo[4];      // Be/Bo: r0,r1 = Bhi; r2,r3 = Blo
                    ldmx4(Ah, aB + kt * 32);
                    ldmx4(Be, bE + kt * 32);
                    ldmx4(Bo, bO + kt * 32);
                    mma16816(De, Ah, Be);
                    mma16816(Do, Ah, Bo);
                    mma16816(De, Ah, Be + 2);
                    mma16816(Do, Ah, Bo + 2);
                }
                // epilogue -> A2 fragment (rows g/g+8, k16 chunk kc of layer-2)
                int ce = kc * 16 + t2;
                float c0 = sC[ce], c1 = sC[ce + 1], c2 = sC[ce + 8], c3 = sC[ce + 9];
                __half2 a0 = __floats2half2_rn(sigf(De[0] + c0), sigf(De[1] + c1));
                __half2 a1 = __floats2half2_rn(sigf(De[2] + c0), sigf(De[3] + c1));
                __half2 a2 = __floats2half2_rn(sigf(Do[0] + c2), sigf(Do[1] + c3));
                __half2 a3 = __floats2half2_rn(sigf(Do[2] + c2), sigf(Do[3] + c3));
                unsigned A2[4] = { *(unsigned*)&a0, *(unsigned*)&a1,
                                   *(unsigned*)&a2, *(unsigned*)&a3 };
                // W2 fragments: two n-tile pairs via x4, last n-tile via x2
                unsigned Bw01[4], Bw23[4], Bw4[2];
                ldmx4(Bw01, wComb + (unsigned)(kc * 32));
                ldmx4(Bw23, wComb + 16u * HS + (unsigned)(kc * 32));
                ldmx2(Bw4,  w4Base + (unsigned)(kc * 32));
                mma16816(D2[0], A2, Bw01);
                mma16816(D2[1], A2, Bw01 + 2);
                mma16816(D2[2], A2, Bw23);
                mma16816(D2[3], A2, Bw23 + 2);
                mma16816(D2[4], A2, Bw4);
            }

            // ---- scores: sigmoid(D2 + b2) . Wd, reduce over n within lane quad
            float p0 = 0.f, p1 = 0.f;
            #pragma unroll
            for (int n = 0; n < 5; n++) {
                int j0 = n * 8 + t2;
                float w0 = sWd[j0], w1 = sWd[j0 + 1];
                float bb0 = sB2[j0], bb1 = sB2[j0 + 1];
                p0 += sigf(D2[n][0] + bb0) * w0 + sigf(D2[n][1] + bb1) * w1;
                p1 += sigf(D2[n][2] + bb0) * w0 + sigf(D2[n][3] + bb1) * w1;
            }
            p0 += __shfl_xor_sync(0xFFFFFFFFu, p0, 1);
            p0 += __shfl_xor_sync(0xFFFFFFFFu, p0, 2);
            p1 += __shfl_xor_sync(0xFFFFFFFFu, p1, 1);
            p1 += __shfl_xor_sync(0xFFFFFFFFu, p1, 2);
            if ((lane & 3) == 0) {
                sSc[wid * 16 + g]     = p0 + bd;
                sSc[wid * 16 + g + 8] = p1 + bd;
            }
        }
        __syncthreads();

        // ---- pooling: out[e] += sum_{t<hlen} score[t] * keys[t][e]  (exact fp32, L2-hot)
        {
            const float* kb2 = keys + (size_t)b * (T_ * E_) + HALF * hh * E_;
            for (int t = wid; t < hlen; t += 8) {
                float sv = sSc[t];
                float2 kv = *(const float2*)(kb2 + (size_t)t * E_ + 2 * lane);
                acc0 += sv * kv.x;
                acc1 += sv * kv.y;
            }
        }
        // no barrier needed: next phase writes only K (not read here), and the
        // next sSc write is behind the post-convert barrier.
    }

    // ---- final reduce across warps
    sSp[wid * 64 + 2 * lane]     = acc0;
    sSp[wid * 64 + 2 * lane + 1] = acc1;
    __syncthreads();
    if (tid < E_) {
        float o = 0.f;
        #pragma unroll
        for (int w = 0; w < 8; w++) o += sSp[w * 64 + tid];
        out[b * E_ + tid] = o;
    }
}

// ---------------------------------------------------------------------------
extern "C" void kernel_launch(void* const* d_in, const int* in_sizes, int n_in,
                              void* d_out, int out_size) {
    const float* query = (const float*)d_in[0];
    const float* keys  = (const float*)d_in[1];
    const int*   klen  = (const int*)  d_in[2];
    const float* W1    = (const float*)d_in[3];
    const float* b1    = (const float*)d_in[4];
    const float* W2    = (const float*)d_in[5];
    const float* b2    = (const float*)d_in[6];
    const float* Wd    = (const float*)d_in[7];
    const float* bd    = (const float*)d_in[8];
    float* out = (float*)d_out;

    cudaFuncSetAttribute(din_mma, cudaFuncAttributeMaxDynamicSharedMemorySize, SMEM_TOTAL);

    prep<<<28, 256>>>(W1, W2, klen);
    din_mma<<<B_, NT, SMEM_TOTAL>>>(query, keys, b1, b2, Wd, bd, out);
}

// round 10
// speedup vs baseline: 1.4925x; 1.1864x over previous
#include <cuda_runtime.h>
#include <cuda_fp16.h>
#include <math.h>

#define B_   4096
#define T_   200
#define E_   64
#define H1_  80
#define H2_  40
#define NT   256
#define HROWS 128
#define HALF  128

// strides (bytes): K/M rows = 144B (144%128=16 -> ldmatrix conflict-free)
//                  W2 rows  = 176B (176%128=48 -> conflict-free)
#define KS  144
#define HS  176

// ---------------- smem layout (bytes)
#define OFF_K   0                       // [128][72]h  18432
#define OFF_M   18432                   // [80][72]h   11520 (fp16, single)
#define OFF_W2  29952                   // [40][88]h    7040
#define OFF_C   36992                   // f32[80]
#define OFF_B2  37312                   // f32[40]
#define OFF_WD  37472                   // f32[40]
#define OFF_Q   37632                   // f32[64]
#define OFF_SC  37888                   // f32[128]
#define OFF_SP  38400                   // f32[8*64]
#define OFF_BD  40448
#define SMEM_TOTAL 40576                // x4 CTAs = 162KB smem -> 66KB L1D carveout

__device__ __forceinline__ unsigned smem_u32(const void* p) {
    unsigned a; asm("{ .reg .u64 t; cvta.to.shared.u64 t, %1; cvt.u32.u64 %0, t; }" : "=r"(a) : "l"(p));
    return a;
}
__device__ __forceinline__ void ldmx4(unsigned a[4], unsigned addr) {
    asm volatile("ldmatrix.sync.aligned.m8n8.x4.shared.b16 {%0,%1,%2,%3}, [%4];"
                 : "=r"(a[0]), "=r"(a[1]), "=r"(a[2]), "=r"(a[3]) : "r"(addr));
}
__device__ __forceinline__ void ldmx2(unsigned a[2], unsigned addr) {
    asm volatile("ldmatrix.sync.aligned.m8n8.x2.shared.b16 {%0,%1}, [%2];"
                 : "=r"(a[0]), "=r"(a[1]) : "r"(addr));
}
__device__ __forceinline__ void mma16816(float d[4], const unsigned a[4], const unsigned b[2]) {
    asm volatile("mma.sync.aligned.m16n8k16.row.col.f32.f16.f16.f32 "
                 "{%0,%1,%2,%3},{%4,%5,%6,%7},{%8,%9},{%0,%1,%2,%3};"
                 : "+f"(d[0]), "+f"(d[1]), "+f"(d[2]), "+f"(d[3])
                 : "r"(a[0]), "r"(a[1]), "r"(a[2]), "r"(a[3]), "r"(b[0]), "r"(b[1]));
}
// sigmoid(x) = 0.5*tanh(0.5x)+0.5 : FMUL + MUFU.TANH + FFMA (1 MUFU vs 2)
__device__ __forceinline__ float sigf(float x) {
    float t;
    asm("tanh.approx.f32 %0, %1;" : "=f"(t) : "f"(0.5f * x));
    return fmaf(0.5f, t, 0.5f);
}

// ---------------- device scratch
__device__ float    g_Wkt[H1_ * E_];   // (W1b - W1c)^T [h][e]
__device__ float    g_Wpt[H1_ * E_];   // W1d^T        [h][e]
__device__ float    g_Wqt[H1_ * E_];   // (W1a + W1c)^T[h][e]
__device__ unsigned g_W2h[1760];       // W2^T fp16 image [40 rows j][88 cols h], u32 words
__device__ int      g_len[B_];

// ---------------------------------------------------------------------------
__global__ void prep(const float* __restrict__ W1, const float* __restrict__ W2,
                     const int* __restrict__ raw) {
    int blk = blockIdx.x, tid = threadIdx.x;
    if (blk < 20) {                                   // W1 folds, transposed
        int idx = blk * 256 + tid;
        if (idx >= H1_ * E_) return;
        int h = idx >> 6, e = idx & 63;
        float wa = W1[(e         ) * H1_ + h];
        float wb = W1[(E_     + e) * H1_ + h];
        float wc = W1[(2 * E_ + e) * H1_ + h];
        float wd = W1[(3 * E_ + e) * H1_ + h];
        g_Wqt[idx] = wa + wc;
        g_Wkt[idx] = wb - wc;
        g_Wpt[idx] = wd;
    } else if (blk == 20) {                           // keys_length dtype sniff + clamp
        int any = 0;
        for (int i = 2 * tid + 1; i < B_; i += 512) any |= raw[i];
        int has_odd = __syncthreads_or(any);
        int is64 = (has_odd == 0);
        for (int i = tid; i < B_; i += 256) {
            int v = is64 ? raw[2 * i] : raw[i];
            g_len[i] = v < 0 ? 0 : (v > T_ ? T_ : v);
        }
    } else {                                          // W2^T fp16 image
        int idx = (blk - 21) * 256 + tid;
        if (idx < 1760) {
            int j = idx / 44, w = idx - j * 44;
            int h0 = 2 * w;
            float v0 = (h0     < H1_) ? W2[h0 * H2_ + j]       : 0.f;
            float v1 = (h0 + 1 < H1_) ? W2[(h0 + 1) * H2_ + j] : 0.f;
            __half2 p = __floats2half2_rn(v0, v1);
            g_W2h[idx] = *(unsigned*)&p;
        }
    }
}

// ---------------------------------------------------------------------------
extern __shared__ char smem[];

__global__ void __launch_bounds__(NT, 4)
din_mma(const float* __restrict__ query, const float* __restrict__ keys,
        const float* __restrict__ b1v,   const float* __restrict__ b2v,
        const float* __restrict__ Wdv,   const float* __restrict__ bdv,
        float* __restrict__ out)
{
    const int tid  = threadIdx.x;
    const int wid  = tid >> 5;
    const int lane = tid & 31;
    const int b    = blockIdx.x;
    const int len  = g_len[b];
    const unsigned sb = smem_u32(smem);

    // fragment lane constants
    const int g     = lane >> 2;
    const int t2    = (lane & 3) * 2;
    const int arow  = (lane & 7) + ((lane >> 3) & 1) * 8;
    const int acolB = ((lane >> 4) * 8) * 2;
    const int brow  = lane & 7;
    const int bcolB = ((lane >> 3) & 1) * 16;

    float* sQ  = (float*)(smem + OFF_Q);
    float* sC  = (float*)(smem + OFF_C);
    float* sB2 = (float*)(smem + OFF_B2);
    float* sWd = (float*)(smem + OFF_WD);
    float* sSc = (float*)(smem + OFF_SC);
    float* sSp = (float*)(smem + OFF_SP);

    // ---- phase 0: small vectors
    if (tid < E_) sQ[tid] = query[b * E_ + tid];
    if (tid >= 64 && tid < 64 + H2_) { int j = tid - 64; sB2[j] = b2v[j]; sWd[j] = Wdv[j]; }
    if (tid == 104) *(float*)(smem + OFF_BD) = bdv[0];
    __syncthreads();

    // ---- phase 1: M (single fp16), C, W2 copy
    for (int idx = tid; idx < H1_ * E_; idx += NT) {
        int h = idx >> 6, e = idx & 63;
        float v = g_Wkt[idx] + sQ[e] * g_Wpt[idx];
        *(__half*)(smem + OFF_M + h * KS + e * 2) = __float2half_rn(v);
    }
    if (tid < H1_) {
        const float4* wq = (const float4*)&g_Wqt[tid * E_];
        const float4* q4 = (const float4*)sQ;
        float c = b1v[tid];
        #pragma unroll
        for (int i = 0; i < 16; i++) {
            float4 w = wq[i], q = q4[i];
            c += w.x * q.x + w.y * q.y + w.z * q.z + w.w * q.w;
        }
        sC[tid] = c;
    }
    for (int i = tid; i < 1760; i += NT) ((unsigned*)(smem + OFF_W2))[i] = g_W2h[i];
    __syncthreads();

    const float bd = *(float*)(smem + OFF_BD);
    float acc0 = 0.f, acc1 = 0.f;          // pooling accumulators (e = 2*lane, 2*lane+1)

    // combined ldmatrix.x4 bases:
    //  - M: lanes 0-15 -> even n-tile (rows +0), lanes 16-31 -> odd n-tile (rows +8)
    //  - W2: lanes 0-15 -> n-tile pair lo, lanes 16-31 -> pair hi
    const unsigned bComb = sb + OFF_M + ((lane & 16) ? 8u * KS : 0u)
                         + (unsigned)brow * KS + bcolB;
    const unsigned wComb = sb + OFF_W2 + ((lane & 16) ? 8u * HS : 0u)
                         + (unsigned)brow * HS + bcolB;
    const unsigned w4Base = sb + OFF_W2 + (unsigned)(4 * 8 + brow) * HS + bcolB;

    for (int hh = 0; hh < 2; hh++) {
        int hlen = len - HALF * hh;
        if (hlen > HALF) hlen = HALF;
        if (hlen <= 0) break;
        const int mt = (hlen + 15) >> 4;   // m16 tiles this half (<=8)

        // ---- convert K half: fp32 -> fp16; zero only rows [hlen, mt*16)
        {
            int zcnt = (mt * 16 - hlen) * (KS / 4);
            unsigned* zh = (unsigned*)(smem + OFF_K + hlen * KS);
            for (int i = tid; i < zcnt; i += NT) zh[i] = 0;
            const float4* kb = (const float4*)(keys + (size_t)b * (T_ * E_) + HALF * hh * E_);
            int n4 = hlen * 16;
            for (int i4 = tid; i4 < n4; i4 += NT) {
                float4 v = kb[i4];
                int tl = i4 >> 4, e4 = (i4 & 15) << 2;
                __half2 h0 = __floats2half2_rn(v.x, v.y);
                __half2 h1 = __floats2half2_rn(v.z, v.w);
                *(uint2*)(smem + OFF_K + (unsigned)tl * KS + (unsigned)e4 * 2) =
                    make_uint2(*(unsigned*)&h0, *(unsigned*)&h1);
            }
        }
        __syncthreads();

        // ---- fused layer1+layer2: warp w owns m-tile w through both layers.
        if (wid < mt) {
            const unsigned aB = sb + OFF_K + (unsigned)(wid * 16 + arow) * KS + acolB;

            float D2[5][4];
            #pragma unroll
            for (int n = 0; n < 5; n++) {          // fold b2 into init
                int j0 = n * 8 + t2;
                float bb0 = sB2[j0], bb1 = sB2[j0 + 1];
                D2[n][0] = bb0; D2[n][1] = bb1; D2[n][2] = bb0; D2[n][3] = bb1;
            }

            #pragma unroll
            for (int kc = 0; kc < 5; kc++) {       // k-chunk = n-tile pair (2kc, 2kc+1)
                int ce = kc * 16 + t2;             // fold C into init
                float c0 = sC[ce], c1 = sC[ce + 1], c2 = sC[ce + 8], c3 = sC[ce + 9];
                float De[4] = {c0, c1, c0, c1};
                float Do[4] = {c2, c3, c2, c3};
                unsigned bB = bComb + (unsigned)(kc * 16) * KS;
                #pragma unroll
                for (int kt = 0; kt < 4; kt++) {
                    unsigned Ah[4], B4[4];         // B4: r0,r1 = even n-tile; r2,r3 = odd
                    ldmx4(Ah, aB + kt * 32);
                    ldmx4(B4, bB + kt * 32);
                    mma16816(De, Ah, B4);
                    mma16816(Do, Ah, B4 + 2);
                }
                // epilogue -> A2 fragment (rows g/g+8, k16 chunk kc of layer-2)
                __half2 a0 = __floats2half2_rn(sigf(De[0]), sigf(De[1]));
                __half2 a1 = __floats2half2_rn(sigf(De[2]), sigf(De[3]));
                __half2 a2 = __floats2half2_rn(sigf(Do[0]), sigf(Do[1]));
                __half2 a3 = __floats2half2_rn(sigf(Do[2]), sigf(Do[3]));
                unsigned A2[4] = { *(unsigned*)&a0, *(unsigned*)&a1,
                                   *(unsigned*)&a2, *(unsigned*)&a3 };
                // W2 fragments: two n-tile pairs via x4, last n-tile via x2
                unsigned Bw01[4], Bw23[4], Bw4[2];
                ldmx4(Bw01, wComb + (unsigned)(kc * 32));
                ldmx4(Bw23, wComb + 16u * HS + (unsigned)(kc * 32));
                ldmx2(Bw4,  w4Base + (unsigned)(kc * 32));
                mma16816(D2[0], A2, Bw01);
                mma16816(D2[1], A2, Bw01 + 2);
                mma16816(D2[2], A2, Bw23);
                mma16816(D2[3], A2, Bw23 + 2);
                mma16816(D2[4], A2, Bw4);
            }

            // ---- scores: sigmoid(D2) . Wd, reduce over n within lane quad
            float p0 = 0.f, p1 = 0.f;
            #pragma unroll
            for (int n = 0; n < 5; n++) {
                int j0 = n * 8 + t2;
                float w0 = sWd[j0], w1 = sWd[j0 + 1];
                p0 += sigf(D2[n][0]) * w0 + sigf(D2[n][1]) * w1;
                p1 += sigf(D2[n][2]) * w0 + sigf(D2[n][3]) * w1;
            }
            p0 += __shfl_xor_sync(0xFFFFFFFFu, p0, 1);
            p0 += __shfl_xor_sync(0xFFFFFFFFu, p0, 2);
            p1 += __shfl_xor_sync(0xFFFFFFFFu, p1, 1);
            p1 += __shfl_xor_sync(0xFFFFFFFFu, p1, 2);
            if ((lane & 3) == 0) {
                sSc[wid * 16 + g]     = p0 + bd;
                sSc[wid * 16 + g + 8] = p1 + bd;
            }
        }
        __syncthreads();

        // ---- pooling: out[e] += sum_{t<hlen} score[t] * keys[t][e]  (exact fp32, L1/L2-hot)
        {
            const float* kb2 = keys + (size_t)b * (T_ * E_) + HALF * hh * E_;
            for (int t = wid; t < hlen; t += 8) {
                float sv = sSc[t];
                float2 kv = *(const float2*)(kb2 + (size_t)t * E_ + 2 * lane);
                acc0 += sv * kv.x;
                acc1 += sv * kv.y;
            }
        }
        // no barrier needed: next phase writes only K (not read here), and the
        // next sSc write is behind the post-convert barrier.
    }

    // ---- final reduce across warps
    sSp[wid * 64 + 2 * lane]     = acc0;
    sSp[wid * 64 + 2 * lane + 1] = acc1;
    __syncthreads();
    if (tid < E_) {
        float o = 0.f;
        #pragma unroll
        for (int w = 0; w < 8; w++) o += sSp[w * 64 + tid];
        out[b * E_ + tid] = o;
    }
}

// ---------------------------------------------------------------------------
extern "C" void kernel_launch(void* const* d_in, const int* in_sizes, int n_in,
                              void* d_out, int out_size) {
    const float* query = (const float*)d_in[0];
    const float* keys  = (const float*)d_in[1];
    const int*   klen  = (const int*)  d_in[2];
    const float* W1    = (const float*)d_in[3];
    const float* b1    = (const float*)d_in[4];
    const float* W2    = (const float*)d_in[5];
    const float* b2    = (const float*)d_in[6];
    const float* Wd    = (const float*)d_in[7];
    const float* bd    = (const float*)d_in[8];
    float* out = (float*)d_out;

    cudaFuncSetAttribute(din_mma, cudaFuncAttributeMaxDynamicSharedMemorySize, SMEM_TOTAL);

    prep<<<28, 256>>>(W1, W2, klen);
    din_mma<<<B_, NT, SMEM_TOTAL>>>(query, keys, b1, b2, Wd, bd, out);
}

// round 11
// speedup vs baseline: 1.7106x; 1.1462x over previous
#include <cuda_runtime.h>
#include <cuda_fp16.h>
#include <math.h>

#define B_   4096
#define T_   200
#define E_   64
#define H1_  80
#define H2_  40
#define NT   256
#define HROWS 128
#define HALF  128

// strides (bytes): K/M rows = 144B (144%128=16 -> ldmatrix conflict-free)
//                  W2 rows  = 176B (176%128=48 -> conflict-free)
#define KS  144
#define HS  176

// ---------------- smem layout (bytes)
#define OFF_K   0                       // [128][72]h  18432
#define OFF_M   18432                   // [80][72]h   11520 (fp16, single)
#define OFF_W2  29952                   // [40][88]h    7040
#define OFF_C   36992                   // f32[80]
#define OFF_B2  37312                   // f32[40]
#define OFF_WD  37472                   // f32[40]
#define OFF_Q   37632                   // f32[64]
#define OFF_SC  37888                   // f32[128]
#define OFF_SP  38400                   // f32[8*64]
#define OFF_BD  40448
#define SMEM_TOTAL 40576                // x4 CTAs = 162KB smem

__device__ __forceinline__ unsigned smem_u32(const void* p) {
    unsigned a; asm("{ .reg .u64 t; cvta.to.shared.u64 t, %1; cvt.u32.u64 %0, t; }" : "=r"(a) : "l"(p));
    return a;
}
__device__ __forceinline__ void ldmx4(unsigned a[4], unsigned addr) {
    asm volatile("ldmatrix.sync.aligned.m8n8.x4.shared.b16 {%0,%1,%2,%3}, [%4];"
                 : "=r"(a[0]), "=r"(a[1]), "=r"(a[2]), "=r"(a[3]) : "r"(addr));
}
__device__ __forceinline__ void ldmx2(unsigned a[2], unsigned addr) {
    asm volatile("ldmatrix.sync.aligned.m8n8.x2.shared.b16 {%0,%1}, [%2];"
                 : "=r"(a[0]), "=r"(a[1]) : "r"(addr));
}
__device__ __forceinline__ void mma16816(float d[4], const unsigned a[4], const unsigned b[2]) {
    asm volatile("mma.sync.aligned.m16n8k16.row.col.f32.f16.f16.f32 "
                 "{%0,%1,%2,%3},{%4,%5,%6,%7},{%8,%9},{%0,%1,%2,%3};"
                 : "+f"(d[0]), "+f"(d[1]), "+f"(d[2]), "+f"(d[3])
                 : "r"(a[0]), "r"(a[1]), "r"(a[2]), "r"(a[3]), "r"(b[0]), "r"(b[1]));
}
// sigmoid(x) = 0.5*tanh(0.5x)+0.5 : FMUL + MUFU.TANH + FFMA
__device__ __forceinline__ float sigf(float x) {
    float t;
    asm("tanh.approx.f32 %0, %1;" : "=f"(t) : "f"(0.5f * x));
    return fmaf(0.5f, t, 0.5f);
}

// ---------------- device scratch
__device__ float    g_Wkt[H1_ * E_];   // (W1b - W1c)^T [h][e]
__device__ float    g_Wpt[H1_ * E_];   // W1d^T        [h][e]
__device__ float    g_Wqt[H1_ * E_];   // (W1a + W1c)^T[h][e]
__device__ unsigned g_W2h[1760];       // W2^T fp16 image [40 rows j][88 cols h], u32 words
__device__ int      g_len[B_];

// ---------------------------------------------------------------------------
__global__ void prep(const float* __restrict__ W1, const float* __restrict__ W2,
                     const int* __restrict__ raw) {
    int blk = blockIdx.x, tid = threadIdx.x;
    if (blk < 20) {                                   // W1 folds, transposed
        int idx = blk * 256 + tid;
        if (idx >= H1_ * E_) return;
        int h = idx >> 6, e = idx & 63;
        float wa = W1[(e         ) * H1_ + h];
        float wb = W1[(E_     + e) * H1_ + h];
        float wc = W1[(2 * E_ + e) * H1_ + h];
        float wd = W1[(3 * E_ + e) * H1_ + h];
        g_Wqt[idx] = wa + wc;
        g_Wkt[idx] = wb - wc;
        g_Wpt[idx] = wd;
    } else if (blk == 20) {                           // keys_length dtype sniff + clamp
        int any = 0;
        for (int i = 2 * tid + 1; i < B_; i += 512) any |= raw[i];
        int has_odd = __syncthreads_or(any);
        int is64 = (has_odd == 0);
        for (int i = tid; i < B_; i += 256) {
            int v = is64 ? raw[2 * i] : raw[i];
            g_len[i] = v < 0 ? 0 : (v > T_ ? T_ : v);
        }
    } else {                                          // W2^T fp16 image
        int idx = (blk - 21) * 256 + tid;
        if (idx < 1760) {
            int j = idx / 44, w = idx - j * 44;
            int h0 = 2 * w;
            float v0 = (h0     < H1_) ? W2[h0 * H2_ + j]       : 0.f;
            float v1 = (h0 + 1 < H1_) ? W2[(h0 + 1) * H2_ + j] : 0.f;
            __half2 p = __floats2half2_rn(v0, v1);
            g_W2h[idx] = *(unsigned*)&p;
        }
    }
}

// ---------------------------------------------------------------------------
extern __shared__ char smem[];

__global__ void __launch_bounds__(NT, 4)
din_mma(const float* __restrict__ query, const float* __restrict__ keys,
        const float* __restrict__ b1v,   const float* __restrict__ b2v,
        const float* __restrict__ Wdv,   const float* __restrict__ bdv,
        float* __restrict__ out)
{
    const int tid  = threadIdx.x;
    const int wid  = tid >> 5;
    const int lane = tid & 31;
    const int b    = blockIdx.x;
    const int len  = g_len[b];
    const unsigned sb = smem_u32(smem);

    // fragment lane constants
    const int g     = lane >> 2;
    const int t2    = (lane & 3) * 2;
    const int arow  = (lane & 7) + ((lane >> 3) & 1) * 8;
    const int acolB = ((lane >> 4) * 8) * 2;
    const int brow  = lane & 7;
    const int bcolB = ((lane >> 3) & 1) * 16;

    float* sQ  = (float*)(smem + OFF_Q);
    float* sC  = (float*)(smem + OFF_C);
    float* sB2 = (float*)(smem + OFF_B2);
    float* sWd = (float*)(smem + OFF_WD);
    float* sSc = (float*)(smem + OFF_SC);
    float* sSp = (float*)(smem + OFF_SP);

    // ---- phase 0: small vectors
    if (tid < E_) sQ[tid] = query[b * E_ + tid];
    if (tid >= 64 && tid < 64 + H2_) { int j = tid - 64; sB2[j] = b2v[j]; sWd[j] = Wdv[j]; }
    if (tid == 104) *(float*)(smem + OFF_BD) = bdv[0];
    __syncthreads();

    // ---- phase 1: M (single fp16), C, W2 copy — static trip counts, unrolled for MLP
    #pragma unroll 5
    for (int r = 0; r < (H1_ * E_) / NT; r++) {        // exactly 20 trips
        int idx = tid + r * NT;
        int h = idx >> 6, e = idx & 63;
        float v = g_Wkt[idx] + sQ[e] * g_Wpt[idx];
        *(__half*)(smem + OFF_M + h * KS + e * 2) = __float2half_rn(v);
    }
    if (tid < H1_) {
        const float4* wq = (const float4*)&g_Wqt[tid * E_];
        const float4* q4 = (const float4*)sQ;
        float c = b1v[tid];
        #pragma unroll
        for (int i = 0; i < 16; i++) {
            float4 w = wq[i], q = q4[i];
            c += w.x * q.x + w.y * q.y + w.z * q.z + w.w * q.w;
        }
        sC[tid] = c;
    }
    #pragma unroll
    for (int r = 0; r < 7; r++) {                      // 1760 = 6.875 * 256
        int i = tid + r * NT;
        if (i < 1760) ((unsigned*)(smem + OFF_W2))[i] = g_W2h[i];
    }
    __syncthreads();

    const float bd = *(float*)(smem + OFF_BD);
    float acc0 = 0.f, acc1 = 0.f;          // pooling accumulators (e = 2*lane, 2*lane+1)

    // combined ldmatrix.x4 bases:
    //  - M: lanes 0-15 -> even n-tile (rows +0), lanes 16-31 -> odd n-tile (rows +8)
    //  - W2: lanes 0-15 -> n-tile pair lo, lanes 16-31 -> pair hi
    const unsigned bComb = sb + OFF_M + ((lane & 16) ? 8u * KS : 0u)
                         + (unsigned)brow * KS + bcolB;
    const unsigned wComb = sb + OFF_W2 + ((lane & 16) ? 8u * HS : 0u)
                         + (unsigned)brow * HS + bcolB;
    const unsigned w4Base = sb + OFF_W2 + (unsigned)(4 * 8 + brow) * HS + bcolB;

    for (int hh = 0; hh < 2; hh++) {
        int hlen = len - HALF * hh;
        if (hlen > HALF) hlen = HALF;
        if (hlen <= 0) break;
        const int mt = (hlen + 15) >> 4;   // m16 tiles this half (<=8)

        // ---- convert K half: fp32 -> fp16; zero only rows [hlen, mt*16)
        {
            int zcnt = (mt * 16 - hlen) * (KS / 4);
            unsigned* zh = (unsigned*)(smem + OFF_K + hlen * KS);
            for (int i = tid; i < zcnt; i += NT) zh[i] = 0;
            const float4* kb = (const float4*)(keys + (size_t)b * (T_ * E_) + HALF * hh * E_);
            int n4 = hlen * 16;
            #pragma unroll 4
            for (int i4 = tid; i4 < n4; i4 += NT) {
                float4 v = kb[i4];
                int tl = i4 >> 4, e4 = (i4 & 15) << 2;
                __half2 h0 = __floats2half2_rn(v.x, v.y);
                __half2 h1 = __floats2half2_rn(v.z, v.w);
                *(uint2*)(smem + OFF_K + (unsigned)tl * KS + (unsigned)e4 * 2) =
                    make_uint2(*(unsigned*)&h0, *(unsigned*)&h1);
            }
        }
        __syncthreads();

        // ---- fused layer1+layer2: warp w owns m-tile w through both layers.
        if (wid < mt) {
            const unsigned aB = sb + OFF_K + (unsigned)(wid * 16 + arow) * KS + acolB;

            float D2[5][4];
            #pragma unroll
            for (int n = 0; n < 5; n++) {          // fold b2 into init
                int j0 = n * 8 + t2;
                float bb0 = sB2[j0], bb1 = sB2[j0 + 1];
                D2[n][0] = bb0; D2[n][1] = bb1; D2[n][2] = bb0; D2[n][3] = bb1;
            }

            #pragma unroll
            for (int kc = 0; kc < 5; kc++) {       // k-chunk = n-tile pair (2kc, 2kc+1)
                int ce = kc * 16 + t2;             // fold C into init
                float c0 = sC[ce], c1 = sC[ce + 1], c2 = sC[ce + 8], c3 = sC[ce + 9];
                float De[4] = {c0, c1, c0, c1};
                float Do[4] = {c2, c3, c2, c3};
                unsigned bB = bComb + (unsigned)(kc * 16) * KS;
                #pragma unroll
                for (int kt = 0; kt < 4; kt++) {
                    unsigned Ah[4], B4[4];         // B4: r0,r1 = even n-tile; r2,r3 = odd
                    ldmx4(Ah, aB + kt * 32);
                    ldmx4(B4, bB + kt * 32);
                    mma16816(De, Ah, B4);
                    mma16816(Do, Ah, B4 + 2);
                }
                // epilogue -> A2 fragment (rows g/g+8, k16 chunk kc of layer-2)
                __half2 a0 = __floats2half2_rn(sigf(De[0]), sigf(De[1]));
                __half2 a1 = __floats2half2_rn(sigf(De[2]), sigf(De[3]));
                __half2 a2 = __floats2half2_rn(sigf(Do[0]), sigf(Do[1]));
                __half2 a3 = __floats2half2_rn(sigf(Do[2]), sigf(Do[3]));
                unsigned A2[4] = { *(unsigned*)&a0, *(unsigned*)&a1,
                                   *(unsigned*)&a2, *(unsigned*)&a3 };
                // W2 fragments: two n-tile pairs via x4, last n-tile via x2
                unsigned Bw01[4], Bw23[4], Bw4[2];
                ldmx4(Bw01, wComb + (unsigned)(kc * 32));
                ldmx4(Bw23, wComb + 16u * HS + (unsigned)(kc * 32));
                ldmx2(Bw4,  w4Base + (unsigned)(kc * 32));
                mma16816(D2[0], A2, Bw01);
                mma16816(D2[1], A2, Bw01 + 2);
                mma16816(D2[2], A2, Bw23);
                mma16816(D2[3], A2, Bw23 + 2);
                mma16816(D2[4], A2, Bw4);
            }

            // ---- scores: sigmoid(D2) . Wd, reduce over n within lane quad
            float p0 = 0.f, p1 = 0.f;
            #pragma unroll
            for (int n = 0; n < 5; n++) {
                int j0 = n * 8 + t2;
                float w0 = sWd[j0], w1 = sWd[j0 + 1];
                p0 += sigf(D2[n][0]) * w0 + sigf(D2[n][1]) * w1;
                p1 += sigf(D2[n][2]) * w0 + sigf(D2[n][3]) * w1;
            }
            p0 += __shfl_xor_sync(0xFFFFFFFFu, p0, 1);
            p0 += __shfl_xor_sync(0xFFFFFFFFu, p0, 2);
            p1 += __shfl_xor_sync(0xFFFFFFFFu, p1, 1);
            p1 += __shfl_xor_sync(0xFFFFFFFFu, p1, 2);
            if ((lane & 3) == 0) {
                sSc[wid * 16 + g]     = p0 + bd;
                sSc[wid * 16 + g + 8] = p1 + bd;
            }
        }
        __syncthreads();

        // ---- pooling: out[e] += sum_{t<hlen} score[t] * keys[t][e]  (exact fp32, L2-hot)
        {
            const float* kb2 = keys + (size_t)b * (T_ * E_) + HALF * hh * E_;
            #pragma unroll 4
            for (int t = wid; t < hlen; t += 8) {
                float sv = sSc[t];
                float2 kv = *(const float2*)(kb2 + (size_t)t * E_ + 2 * lane);
                acc0 += sv * kv.x;
                acc1 += sv * kv.y;
            }
        }
        // no barrier needed: next phase writes only K (not read here), and the
        // next sSc write is behind the post-convert barrier.
    }

    // ---- final reduce across warps
    sSp[wid * 64 + 2 * lane]     = acc0;
    sSp[wid * 64 + 2 * lane + 1] = acc1;
    __syncthreads();
    if (tid < E_) {
        float o = 0.f;
        #pragma unroll
        for (int w = 0; w < 8; w++) o += sSp[w * 64 + tid];
        out[b * E_ + tid] = o;
    }
}

// ---------------------------------------------------------------------------
extern "C" void kernel_launch(void* const* d_in, const int* in_sizes, int n_in,
                              void* d_out, int out_size) {
    const float* query = (const float*)d_in[0];
    const float* keys  = (const float*)d_in[1];
    const int*   klen  = (const int*)  d_in[2];
    const float* W1    = (const float*)d_in[3];
    const float* b1    = (const float*)d_in[4];
    const float* W2    = (const float*)d_in[5];
    const float* b2    = (const float*)d_in[6];
    const float* Wd    = (const float*)d_in[7];
    const float* bd    = (const float*)d_in[8];
    float* out = (float*)d_out;

    cudaFuncSetAttribute(din_mma, cudaFuncAttributeMaxDynamicSharedMemorySize, SMEM_TOTAL);

    prep<<<28, 256>>>(W1, W2, klen);
    din_mma<<<B_, NT, SMEM_TOTAL>>>(query, keys, b1, b2, Wd, bd, out);
}

// round 13
// speedup vs baseline: 1.7943x; 1.0489x over previous
#include <cuda_runtime.h>
#include <cuda_fp16.h>
#include <math.h>

#define B_   4096
#define T_   200
#define E_   64
#define H1_  80
#define H2_  40
#define NT   256
#define HROWS 128
#define HALF  128

// strides (bytes): K/M rows = 144B (144%128=16 -> ldmatrix conflict-free)
//                  W2 rows  = 176B (176%128=48 -> conflict-free)
#define KS  144
#define HS  176

// ---------------- smem layout (bytes)
#define OFF_K   0                       // [128][72]h  18432
#define OFF_M   18432                   // [80][72]h   11520 (fp16, single)
#define OFF_W2  29952                   // [40][88]h    7040
#define OFF_C   36992                   // f32[80]
#define OFF_B2  37312                   // f32[40]
#define OFF_WD  37472                   // f32[40]
#define OFF_Q   37632                   // f32[64]
#define OFF_SC  37888                   // f32[128]
#define OFF_SP  38400                   // f32[8*64]
#define OFF_BD  40448
#define SMEM_TOTAL 40576                // x4 CTAs = 162KB smem

__device__ __forceinline__ unsigned smem_u32(const void* p) {
    unsigned a; asm("{ .reg .u64 t; cvta.to.shared.u64 t, %1; cvt.u32.u64 %0, t; }" : "=r"(a) : "l"(p));
    return a;
}
__device__ __forceinline__ void ldmx4(unsigned a[4], unsigned addr) {
    asm volatile("ldmatrix.sync.aligned.m8n8.x4.shared.b16 {%0,%1,%2,%3}, [%4];"
                 : "=r"(a[0]), "=r"(a[1]), "=r"(a[2]), "=r"(a[3]) : "r"(addr));
}
__device__ __forceinline__ void ldmx2(unsigned a[2], unsigned addr) {
    asm volatile("ldmatrix.sync.aligned.m8n8.x2.shared.b16 {%0,%1}, [%2];"
                 : "=r"(a[0]), "=r"(a[1]) : "r"(addr));
}
__device__ __forceinline__ void mma16816(float d[4], const unsigned a[4], const unsigned b[2]) {
    asm volatile("mma.sync.aligned.m16n8k16.row.col.f32.f16.f16.f32 "
                 "{%0,%1,%2,%3},{%4,%5,%6,%7},{%8,%9},{%0,%1,%2,%3};"
                 : "+f"(d[0]), "+f"(d[1]), "+f"(d[2]), "+f"(d[3])
                 : "r"(a[0]), "r"(a[1]), "r"(a[2]), "r"(a[3]), "r"(b[0]), "r"(b[1]));
}
// sigmoid(x) = 0.5*tanh(0.5x)+0.5 : FMUL + MUFU.TANH + FFMA
__device__ __forceinline__ float sigf(float x) {
    float t;
    asm("tanh.approx.f32 %0, %1;" : "=f"(t) : "f"(0.5f * x));
    return fmaf(0.5f, t, 0.5f);
}

// ---------------- device scratch
__device__ float    g_Wkt[H1_ * E_];   // (W1b - W1c)^T [h][e]
__device__ float    g_Wpt[H1_ * E_];   // W1d^T        [h][e]
__device__ float    g_Wqt[H1_ * E_];   // (W1a + W1c)^T[h][e]
__device__ unsigned g_W2h[1760];       // W2^T fp16 image [40 rows j][88 cols h], u32 words
__device__ int      g_len[B_];

// ---------------------------------------------------------------------------
__global__ void prep(const float* __restrict__ W1, const float* __restrict__ W2,
                     const int* __restrict__ raw) {
    int blk = blockIdx.x, tid = threadIdx.x;
    if (blk < 20) {                                   // W1 folds, transposed
        int idx = blk * 256 + tid;
        if (idx >= H1_ * E_) return;
        int h = idx >> 6, e = idx & 63;
        float wa = W1[(e         ) * H1_ + h];
        float wb = W1[(E_     + e) * H1_ + h];
        float wc = W1[(2 * E_ + e) * H1_ + h];
        float wd = W1[(3 * E_ + e) * H1_ + h];
        g_Wqt[idx] = wa + wc;
        g_Wkt[idx] = wb - wc;
        g_Wpt[idx] = wd;
    } else if (blk == 20) {                           // keys_length dtype sniff + clamp
        int any = 0;
        for (int i = 2 * tid + 1; i < B_; i += 512) any |= raw[i];
        int has_odd = __syncthreads_or(any);
        int is64 = (has_odd == 0);
        for (int i = tid; i < B_; i += 256) {
            int v = is64 ? raw[2 * i] : raw[i];
            g_len[i] = v < 0 ? 0 : (v > T_ ? T_ : v);
        }
    } else {                                          // W2^T fp16 image
        int idx = (blk - 21) * 256 + tid;
        if (idx < 1760) {
            int j = idx / 44, w = idx - j * 44;
            int h0 = 2 * w;
            float v0 = (h0     < H1_) ? W2[h0 * H2_ + j]       : 0.f;
            float v1 = (h0 + 1 < H1_) ? W2[(h0 + 1) * H2_ + j] : 0.f;
            __half2 p = __floats2half2_rn(v0, v1);
            g_W2h[idx] = *(unsigned*)&p;
        }
    }
}

// ---------------------------------------------------------------------------
extern __shared__ char smem[];

__global__ void __launch_bounds__(NT, 4)
din_mma(const float* __restrict__ query, const float* __restrict__ keys,
        const float* __restrict__ b1v,   const float* __restrict__ b2v,
        const float* __restrict__ Wdv,   const float* __restrict__ bdv,
        float* __restrict__ out)
{
    const int tid  = threadIdx.x;
    const int wid  = tid >> 5;
    const int lane = tid & 31;
    const int b    = blockIdx.x;
    const int len  = g_len[b];
    const unsigned sb = smem_u32(smem);

    // fragment lane constants
    const int g     = lane >> 2;
    const int t2    = (lane & 3) * 2;
    const int arow  = (lane & 7) + ((lane >> 3) & 1) * 8;
    const int acolB = ((lane >> 4) * 8) * 2;
    const int brow  = lane & 7;
    const int bcolB = ((lane >> 3) & 1) * 16;

    float* sQ  = (float*)(smem + OFF_Q);
    float* sC  = (float*)(smem + OFF_C);
    float* sB2 = (float*)(smem + OFF_B2);
    float* sWd = (float*)(smem + OFF_WD);
    float* sSc = (float*)(smem + OFF_SC);
    float* sSp = (float*)(smem + OFF_SP);

    // ---- phase 0: small vectors
    if (tid < E_) sQ[tid] = query[b * E_ + tid];
    if (tid >= 64 && tid < 64 + H2_) { int j = tid - 64; sB2[j] = b2v[j]; sWd[j] = Wdv[j]; }
    if (tid == 104) *(float*)(smem + OFF_BD) = bdv[0];
    __syncthreads();

    // ---- phase 1: M (single fp16), C, W2 copy — static trip counts, unrolled for MLP
    #pragma unroll 5
    for (int r = 0; r < (H1_ * E_) / NT; r++) {        // exactly 20 trips
        int idx = tid + r * NT;
        int h = idx >> 6, e = idx & 63;
        float v = g_Wkt[idx] + sQ[e] * g_Wpt[idx];
        *(__half*)(smem + OFF_M + h * KS + e * 2) = __float2half_rn(v);
    }
    if (tid < H1_) {
        const float4* wq = (const float4*)&g_Wqt[tid * E_];
        const float4* q4 = (const float4*)sQ;
        float c = b1v[tid];
        #pragma unroll
        for (int i = 0; i < 16; i++) {
            float4 w = wq[i], q = q4[i];
            c += w.x * q.x + w.y * q.y + w.z * q.z + w.w * q.w;
        }
        sC[tid] = c;
    }
    #pragma unroll
    for (int r = 0; r < 7; r++) {                      // 1760 = 6.875 * 256
        int i = tid + r * NT;
        if (i < 1760) ((unsigned*)(smem + OFF_W2))[i] = g_W2h[i];
    }
    __syncthreads();

    const float bd = *(float*)(smem + OFF_BD);
    const int esub = (lane & 15) * 4;      // pooling: e base for this lane
    float ac0 = 0.f, ac1 = 0.f, ac2 = 0.f, ac3 = 0.f;

    // combined ldmatrix.x4 bases:
    //  - M: lanes 0-15 -> even n-tile (rows +0), lanes 16-31 -> odd n-tile (rows +8)
    //  - W2: lanes 0-15 -> n-tile pair lo, lanes 16-31 -> pair hi
    const unsigned bComb = sb + OFF_M + ((lane & 16) ? 8u * KS : 0u)
                         + (unsigned)brow * KS + bcolB;
    const unsigned wComb = sb + OFF_W2 + ((lane & 16) ? 8u * HS : 0u)
                         + (unsigned)brow * HS + bcolB;
    const unsigned w4Base = sb + OFF_W2 + (unsigned)(4 * 8 + brow) * HS + bcolB;

    for (int hh = 0; hh < 2; hh++) {
        int hlen = len - HALF * hh;
        if (hlen > HALF) hlen = HALF;
        if (hlen <= 0) break;
        const int mt = (hlen + 15) >> 4;   // m16 tiles this half (<=8)

        // ---- convert K half: fp32 -> fp16; zero only rows [hlen, mt*16)
        {
            int zcnt = (mt * 16 - hlen) * (KS / 4);
            unsigned* zh = (unsigned*)(smem + OFF_K + hlen * KS);
            for (int i = tid; i < zcnt; i += NT) zh[i] = 0;
            const float4* kb = (const float4*)(keys + (size_t)b * (T_ * E_) + HALF * hh * E_);
            int n4 = hlen * 16;
            #pragma unroll 4
            for (int i4 = tid; i4 < n4; i4 += NT) {
                float4 v = kb[i4];
                int tl = i4 >> 4, e4 = (i4 & 15) << 2;
                __half2 h0 = __floats2half2_rn(v.x, v.y);
                __half2 h1 = __floats2half2_rn(v.z, v.w);
                *(uint2*)(smem + OFF_K + (unsigned)tl * KS + (unsigned)e4 * 2) =
                    make_uint2(*(unsigned*)&h0, *(unsigned*)&h1);
            }
        }
        __syncthreads();

        // ---- fused layer1+layer2: warp w owns m-tile w through both layers.
        if (wid < mt) {
            const unsigned aB = sb + OFF_K + (unsigned)(wid * 16 + arow) * KS + acolB;

            float D2[5][4];
            #pragma unroll
            for (int n = 0; n < 5; n++) {          // fold b2 into init
                int j0 = n * 8 + t2;
                float bb0 = sB2[j0], bb1 = sB2[j0 + 1];
                D2[n][0] = bb0; D2[n][1] = bb1; D2[n][2] = bb0; D2[n][3] = bb1;
            }

            // ---- kc pairs {0,1},{2,3}: one A-fragment load serves two k-chunks
            #pragma unroll
            for (int p = 0; p < 2; p++) {
                int kc0 = 2 * p, kc1 = 2 * p + 1;
                float2 cA0 = *(float2*)&sC[kc0 * 16 + t2];
                float2 cB0 = *(float2*)&sC[kc0 * 16 + t2 + 8];
                float2 cA1 = *(float2*)&sC[kc1 * 16 + t2];
                float2 cB1 = *(float2*)&sC[kc1 * 16 + t2 + 8];
                float De0[4] = {cA0.x, cA0.y, cA0.x, cA0.y};
                float Do0[4] = {cB0.x, cB0.y, cB0.x, cB0.y};
                float De1[4] = {cA1.x, cA1.y, cA1.x, cA1.y};
                float Do1[4] = {cB1.x, cB1.y, cB1.x, cB1.y};
                unsigned bB0 = bComb + (unsigned)(kc0 * 16) * KS;
                unsigned bB1 = bComb + (unsigned)(kc1 * 16) * KS;
                #pragma unroll
                for (int kt = 0; kt < 4; kt++) {
                    unsigned Ah[4], Ba[4], Bb[4];
                    ldmx4(Ah, aB + kt * 32);
                    ldmx4(Ba, bB0 + kt * 32);
                    mma16816(De0, Ah, Ba);
                    mma16816(Do0, Ah, Ba + 2);
                    ldmx4(Bb, bB1 + kt * 32);
                    mma16816(De1, Ah, Bb);
                    mma16816(Do1, Ah, Bb + 2);
                }
                #pragma unroll
                for (int s = 0; s < 2; s++) {
                    const float* De = s ? De1 : De0;
                    const float* Do = s ? Do1 : Do0;
                    int kc = s ? kc1 : kc0;
                    __half2 a0 = __floats2half2_rn(sigf(De[0]), sigf(De[1]));
                    __half2 a1 = __floats2half2_rn(sigf(De[2]), sigf(De[3]));
                    __half2 a2 = __floats2half2_rn(sigf(Do[0]), sigf(Do[1]));
                    __half2 a3 = __floats2half2_rn(sigf(Do[2]), sigf(Do[3]));
                    unsigned A2[4] = { *(unsigned*)&a0, *(unsigned*)&a1,
                                       *(unsigned*)&a2, *(unsigned*)&a3 };
                    unsigned Bw01[4], Bw23[4], Bw4[2];
                    ldmx4(Bw01, wComb + (unsigned)(kc * 32));
                    ldmx4(Bw23, wComb + 16u * HS + (unsigned)(kc * 32));
                    ldmx2(Bw4,  w4Base + (unsigned)(kc * 32));
                    mma16816(D2[0], A2, Bw01);
                    mma16816(D2[1], A2, Bw01 + 2);
                    mma16816(D2[2], A2, Bw23);
                    mma16816(D2[3], A2, Bw23 + 2);
                    mma16816(D2[4], A2, Bw4);
                }
            }
            // ---- kc = 4 tail
            {
                const int kc = 4;
                float2 cA = *(float2*)&sC[kc * 16 + t2];
                float2 cB = *(float2*)&sC[kc * 16 + t2 + 8];
                float De[4] = {cA.x, cA.y, cA.x, cA.y};
                float Do[4] = {cB.x, cB.y, cB.x, cB.y};
                unsigned bB = bComb + (unsigned)(kc * 16) * KS;
                #pragma unroll
                for (int kt = 0; kt < 4; kt++) {
                    unsigned Ah[4], B4[4];
                    ldmx4(Ah, aB + kt * 32);
                    ldmx4(B4, bB + kt * 32);
                    mma16816(De, Ah, B4);
                    mma16816(Do, Ah, B4 + 2);
                }
                __half2 a0 = __floats2half2_rn(sigf(De[0]), sigf(De[1]));
                __half2 a1 = __floats2half2_rn(sigf(De[2]), sigf(De[3]));
                __half2 a2 = __floats2half2_rn(sigf(Do[0]), sigf(Do[1]));
                __half2 a3 = __floats2half2_rn(sigf(Do[2]), sigf(Do[3]));
                unsigned A2[4] = { *(unsigned*)&a0, *(unsigned*)&a1,
                                   *(unsigned*)&a2, *(unsigned*)&a3 };
                unsigned Bw01[4], Bw23[4], Bw4[2];
                ldmx4(Bw01, wComb + (unsigned)(kc * 32));
                ldmx4(Bw23, wComb + 16u * HS + (unsigned)(kc * 32));
                ldmx2(Bw4,  w4Base + (unsigned)(kc * 32));
                mma16816(D2[0], A2, Bw01);
                mma16816(D2[1], A2, Bw01 + 2);
                mma16816(D2[2], A2, Bw23);
                mma16816(D2[3], A2, Bw23 + 2);
                mma16816(D2[4], A2, Bw4);
            }

            // ---- scores: sigmoid(D2) . Wd, reduce over n within lane quad
            float p0 = 0.f, p1 = 0.f;
            #pragma unroll
            for (int n = 0; n < 5; n++) {
                int j0 = n * 8 + t2;
                float w0 = sWd[j0], w1 = sWd[j0 + 1];
                p0 += sigf(D2[n][0]) * w0 + sigf(D2[n][1]) * w1;
                p1 += sigf(D2[n][2]) * w0 + sigf(D2[n][3]) * w1;
            }
            p0 += __shfl_xor_sync(0xFFFFFFFFu, p0, 1);
            p0 += __shfl_xor_sync(0xFFFFFFFFu, p0, 2);
            p1 += __shfl_xor_sync(0xFFFFFFFFu, p1, 1);
            p1 += __shfl_xor_sync(0xFFFFFFFFu, p1, 2);
            if ((lane & 3) == 0) {
                sSc[wid * 16 + g]     = p0 + bd;
                sSc[wid * 16 + g + 8] = p1 + bd;
            }
        }
        __syncthreads();

        // ---- pooling: 2 rows per warp-iter; lanes 0-15 row t, 16-31 row t+1 (float4)
        {
            const float* kb2 = keys + (size_t)b * (T_ * E_) + HALF * hh * E_;
            const int rofs = lane >> 4;        // 0 or 1
            #pragma unroll 4
            for (int t = 2 * wid; t < hlen; t += 16) {
                int row = t + rofs;
                if (row < hlen) {
                    float sv = sSc[row];
                    float4 kv = *(const float4*)(kb2 + (size_t)row * E_ + esub);
                    ac0 += sv * kv.x;
                    ac1 += sv * kv.y;
                    ac2 += sv * kv.z;
                    ac3 += sv * kv.w;
                }
            }
        }
        // no barrier needed: next phase writes only K (not read here), and the
        // next sSc write is behind the post-convert barrier.
    }

    // ---- final reduce across warps (combine row-parity halves first)
    ac0 += __shfl_down_sync(0xFFFFFFFFu, ac0, 16);
    ac1 += __shfl_down_sync(0xFFFFFFFFu, ac1, 16);
    ac2 += __shfl_down_sync(0xFFFFFFFFu, ac2, 16);
    ac3 += __shfl_down_sync(0xFFFFFFFFu, ac3, 16);
    if (lane < 16) {
        float4 v = make_float4(ac0, ac1, ac2, ac3);
        *(float4*)&sSp[wid * 64 + esub] = v;
    }
    __syncthreads();
    if (tid < E_) {
        float o = 0.f;
        #pragma unroll
        for (int w = 0; w < 8; w++) o += sSp[w * 64 + tid];
        out[b * E_ + tid] = o;
    }
}

// ---------------------------------------------------------------------------
extern "C" void kernel_launch(void* const* d_in, const int* in_sizes, int n_in,
                              void* d_out, int out_size) {
    const float* query = (const float*)d_in[0];
    const float* keys  = (const float*)d_in[1];
    const int*   klen  = (const int*)  d_in[2];
    const float* W1    = (const float*)d_in[3];
    const float* b1    = (const float*)d_in[4];
    const float* W2    = (const float*)d_in[5];
    const float* b2    = (const float*)d_in[6];
    const float* Wd    = (const float*)d_in[7];
    const float* bd    = (const float*)d_in[8];
    float* out = (float*)d_out;

    cudaFuncSetAttribute(din_mma, cudaFuncAttributeMaxDynamicSharedMemorySize, SMEM_TOTAL);

    prep<<<28, 256>>>(W1, W2, klen);
    din_mma<<<B_, NT, SMEM_TOTAL>>>(query, keys, b1, b2, Wd, bd, out);
}